// round 2
// baseline (speedup 1.0000x reference)
#include <cuda_runtime.h>
#include <math.h>

#define NBOX   4096
#define NFRAME 4
#define CAP    128
#define MAXC   16
#define LISTCAP 49152
#define IOU_T   0.3f
#define SCORE_T 0.2f

// ---------------- scratch (static __device__, no allocations) ----------------
__device__ float d_sbox  [NFRAME*NBOX*7];
__device__ float d_sscore[NFRAME*NBOX];
__device__ float d_slabel[NFRAME*NBOX];
__device__ float d_x1[NFRAME*NBOX], d_x2[NFRAME*NBOX];
__device__ float d_y1[NFRAME*NBOX], d_y2[NFRAME*NBOX];
__device__ float d_areaA[NFRAME*NBOX];
__device__ int   d_V[NFRAME];
__device__ int   d_nbr[NFRAME*NBOX*CAP];
__device__ int   d_deg[NFRAME*NBOX];
__device__ int   d_clusIdx[NFRAME*NBOX*MAXC];
__device__ int   d_count[NFRAME*NBOX];
__device__ int   d_lead[NFRAME*NBOX];

// ---------------- kernel 1: stable sort by score desc + gather --------------
__global__ void __launch_bounds__(1024) k_sort(const float* __restrict__ boxes,
                                               const float* __restrict__ scores,
                                               const int*   __restrict__ labels)
{
    int f = blockIdx.x, tid = threadIdx.x;
    __shared__ unsigned long long key[NBOX];
    __shared__ int vcount;
    const float* sc = scores + f*NBOX;
    if (tid == 0) vcount = 0;
    for (int i = tid; i < NBOX; i += 1024) {
        float s    = sc[i];
        float skey = (s > SCORE_T) ? s : -INFINITY;
        unsigned u = __float_as_uint(skey);
        u = (u & 0x80000000u) ? ~u : (u | 0x80000000u);   // ascending-sortable
        key[i] = ((unsigned long long)(~u) << 32) | (unsigned)i; // desc score, asc idx (stable)
    }
    __syncthreads();
    for (int k = 2; k <= NBOX; k <<= 1) {
        for (int j = k >> 1; j > 0; j >>= 1) {
            for (int i = tid; i < NBOX; i += 1024) {
                int ixj = i ^ j;
                if (ixj > i) {
                    unsigned long long a = key[i], b = key[ixj];
                    bool up = ((i & k) == 0);
                    if ((a > b) == up) { key[i] = b; key[ixj] = a; }
                }
            }
            __syncthreads();
        }
    }
    for (int r = tid; r < NBOX; r += 1024) {
        int o = (int)(key[r] & 0xFFFFFFFFu);
        const float* bx = boxes + ((size_t)f*NBOX + o)*7;
        float b0 = bx[0], b1 = bx[1], b2 = bx[2], b3 = bx[3],
              b4 = bx[4], b5 = bx[5], b6 = bx[6];
        float s  = sc[o];
        int  lab = labels[f*NBOX + o];
        float off = (float)lab * 10000.0f;          // exact for lab in {0,1,2}
        float cx = b0 + off, cy = b1;
        float hx = b3 * 0.5f, hy = b4 * 0.5f;
        float x1 = cx - hx, x2 = cx + hx, y1 = cy - hy, y2 = cy + hy;
        float area = (x2 - x1) * (y2 - y1);         // replicate reference op order
        int idx = f*NBOX + r;
        float* sb = d_sbox + (size_t)idx*7;
        sb[0]=b0; sb[1]=b1; sb[2]=b2; sb[3]=b3; sb[4]=b4; sb[5]=b5; sb[6]=b6;
        d_sscore[idx] = s; d_slabel[idx] = (float)lab;
        d_x1[idx]=x1; d_x2[idx]=x2; d_y1[idx]=y1; d_y2[idx]=y2; d_areaA[idx]=area;
        if (s > SCORE_T) atomicAdd(&vcount, 1);
    }
    __syncthreads();
    if (tid == 0) d_V[f] = vcount;
}

// ---------------- kernel 2: ascending neighbor lists (IoU > thres) ----------
__global__ void __launch_bounds__(128) k_nbr()
{
    int f   = blockIdx.y;
    int V   = d_V[f];
    int i0  = blockIdx.x * 128;
    int tid = threadIdx.x;
    int i   = i0 + tid;
    int base = f*NBOX;
    bool act = (i < V);
    if (i < NBOX && !act) d_deg[base + i] = 0;
    if (i0 >= V) return;

    float xi1=0,xi2=0,yi1=0,yi2=0,ai=0;
    if (act) { xi1=d_x1[base+i]; xi2=d_x2[base+i];
               yi1=d_y1[base+i]; yi2=d_y2[base+i]; ai=d_areaA[base+i]; }
    __shared__ float sx1[128], sx2[128], sy1[128], sy2[128], sa[128];
    int  cnt  = 0;
    int* lst  = d_nbr + ((size_t)(base + i)) * CAP;
    for (int j0 = 0; j0 < V; j0 += 128) {
        __syncthreads();
        int j = j0 + tid;
        if (j < V) { sx1[tid]=d_x1[base+j]; sx2[tid]=d_x2[base+j];
                     sy1[tid]=d_y1[base+j]; sy2[tid]=d_y2[base+j]; sa[tid]=d_areaA[base+j]; }
        __syncthreads();
        int lim = min(128, V - j0);
        if (act) {
            for (int jj = 0; jj < lim; ++jj) {
                float ix = fminf(xi2, sx2[jj]) - fmaxf(xi1, sx1[jj]);
                if (ix > 0.f) {
                    float iy = fminf(yi2, sy2[jj]) - fmaxf(yi1, sy1[jj]);
                    if (iy > 0.f) {
                        float inter = ix * iy;
                        float den   = fmaxf(ai + sa[jj] - inter, 1e-6f);
                        float iou   = inter / den;          // exact fp32 div, matches ref
                        if (iou > IOU_T && cnt < CAP) lst[cnt++] = j0 + jj;
                    }
                }
            }
        }
    }
    if (act) d_deg[base + i] = cnt;
}

// ---------------- kernel 3: sequential greedy claim (warp 0) ----------------
__global__ void __launch_bounds__(1024) k_scan()
{
    extern __shared__ int smem[];
    int* soff  = smem;                       // NBOX+1
    int* slist = smem + NBOX + 1;            // LISTCAP
    unsigned char* alive = (unsigned char*)(smem + NBOX + 1 + LISTCAP); // NBOX
    __shared__ int wsum[32];

    int f = blockIdx.x, tid = threadIdx.x;
    int base = f*NBOX;
    int V = d_V[f];

    for (int i = tid; i < NBOX; i += 1024) {
        d_lead[base + i] = 0;
        alive[i] = (i < V) ? (unsigned char)1 : (unsigned char)0;
    }
    // prefix sum of deg (4 items per thread)
    int i0 = tid * 4;
    int dv[4]; int ssum = 0;
    #pragma unroll
    for (int u = 0; u < 4; ++u) { dv[u] = d_deg[base + i0 + u]; ssum += dv[u]; }
    int lane = tid & 31, wid = tid >> 5;
    int x = ssum;
    #pragma unroll
    for (int o = 1; o < 32; o <<= 1) { int y = __shfl_up_sync(0xffffffffu, x, o); if (lane >= o) x += y; }
    if (lane == 31) wsum[wid] = x;
    __syncthreads();
    if (wid == 0) {
        int v = wsum[lane];
        #pragma unroll
        for (int o = 1; o < 32; o <<= 1) { int y = __shfl_up_sync(0xffffffffu, v, o); if (lane >= o) v += y; }
        wsum[lane] = v;
    }
    __syncthreads();
    int excl = x - ssum + (wid ? wsum[wid - 1] : 0);
    int run = excl;
    #pragma unroll
    for (int u = 0; u < 4; ++u) { soff[i0 + u] = run; run += dv[u]; }
    if (tid == 1023) soff[NBOX] = run;
    __syncthreads();
    // compact neighbor lists into shared (fallback: stay in global if overflow)
    for (int i = tid; i < NBOX; i += 1024) {
        int off = soff[i]; int dg = soff[i + 1] - off;
        if (dg > 0 && off + dg <= LISTCAP) {
            const int* g = d_nbr + ((size_t)(base + i)) * CAP;
            for (int k = 0; k < dg; ++k) slist[off + k] = g[k];
        }
    }
    __syncthreads();
    if (tid >= 32) return;   // warp 0 runs the serial scan

    for (int i = 0; i < V; ++i) {
        __syncwarp();
        if (!alive[i]) continue;             // uniform (all lanes read same byte)
        int off = soff[i]; int dg = soff[i + 1] - off;
        bool insh = (off + dg) <= LISTCAP;
        const int* g = d_nbr + ((size_t)(base + i)) * CAP;
        int rb = 0;
        for (int c = 0; c < dg; c += 32) {
            int idx = c + lane;
            int nb = -1;
            if (idx < dg) nb = insh ? slist[off + idx] : g[idx];
            bool cl = (nb >= 0) && alive[nb];
            unsigned m = __ballot_sync(0xffffffffu, cl);
            if (cl) {
                int r = rb + __popc(m & ((1u << lane) - 1u));
                alive[nb] = 0;
                if (r < MAXC) d_clusIdx[(base + i)*MAXC + r] = nb;
            }
            rb += __popc(m);
            __syncwarp();
        }
        if (lane == 0) { d_count[base + i] = rb < MAXC ? rb : MAXC; d_lead[base + i] = 1; }
    }
}

// ---------------- kernel 4: MLP + softmax merge + output --------------------
__global__ void __launch_bounds__(256) k_merge(const float* __restrict__ W1,
                                               const float* __restrict__ b1,
                                               const float* __restrict__ W2,
                                               const float* __restrict__ b2,
                                               float* __restrict__ out, int writeLead)
{
    __shared__ float sW1[448], sb1[64], sW2[64];
    __shared__ float sb2;
    int tid = threadIdx.x;
    for (int t = tid; t < 448; t += 256) sW1[t] = W1[t];
    if (tid < 64) { sb1[tid] = b1[tid]; sW2[tid] = W2[tid]; }
    if (tid == 0) sb2 = b2[0];
    __syncthreads();

    int g = tid >> 4, l = tid & 15;
    unsigned gm = 0xFFFFu << (tid & 16);     // 16-lane group mask
    int row = blockIdx.x * 16 + g;           // f*NBOX + r
    float* infoOut = out + (size_t)row * 9;
    int lead = d_lead[row];
    if (!lead) {
        if (l == 0) {
            #pragma unroll
            for (int d = 0; d < 9; ++d) infoOut[d] = 0.f;
            if (writeLead) out[(size_t)NFRAME*NBOX*9 + row] = 0.f;
        }
        return;
    }
    int cnt = d_count[row];
    bool ok = l < cnt;
    float c[7];
    int f = row >> 12;
    if (ok) {
        int nb = d_clusIdx[row*MAXC + l];
        const float* sp = d_sbox + ((size_t)(f*NBOX) + nb) * 7;
        #pragma unroll
        for (int d = 0; d < 7; ++d) c[d] = sp[d];
    } else {
        #pragma unroll
        for (int d = 0; d < 7; ++d) c[d] = 0.f;
    }
    float logit;
    if (ok) {
        float lg = 0.f;
        for (int k = 0; k < 64; ++k) {
            float h = sb1[k];
            #pragma unroll
            for (int d = 0; d < 7; ++d) h += c[d] * sW1[d*64 + k];
            h = fmaxf(h, 0.f);
            lg += h * sW2[k];
        }
        logit = lg + sb2;
    } else logit = -1e9f;

    float m = logit;
    #pragma unroll
    for (int o = 8; o; o >>= 1) m = fmaxf(m, __shfl_xor_sync(gm, m, o, 16));
    float p = ok ? expf(logit - m) : 0.f;
    float S = p;
    #pragma unroll
    for (int o = 8; o; o >>= 1) S += __shfl_xor_sync(gm, S, o, 16);
    float w = p / S;
    float mg[7];
    #pragma unroll
    for (int d = 0; d < 7; ++d) {
        float v = w * c[d];
        #pragma unroll
        for (int o = 8; o; o >>= 1) v += __shfl_xor_sync(gm, v, o, 16);
        mg[d] = v;
    }
    if (l == 0) {
        const float* own = d_sbox + (size_t)row * 7;
        infoOut[0] = mg[0]; infoOut[1] = mg[1]; infoOut[2] = mg[2];
        infoOut[3] = (mg[3] <= 0.f) ? own[3] : mg[3];
        infoOut[4] = (mg[4] <= 0.f) ? own[4] : mg[4];
        infoOut[5] = (mg[5] <= 0.f) ? own[5] : mg[5];
        infoOut[6] = mg[6];
        infoOut[7] = d_sscore[row];
        infoOut[8] = d_slabel[row];
        if (writeLead) out[(size_t)NFRAME*NBOX*9 + row] = 1.f;
    }
}

// ---------------- launch -----------------------------------------------------
extern "C" void kernel_launch(void* const* d_in, const int* in_sizes, int n_in,
                              void* d_out, int out_size)
{
    const float* boxes  = (const float*)d_in[0];
    const float* scores = (const float*)d_in[1];
    const int*   labels = (const int*)  d_in[2];
    const float* W1     = (const float*)d_in[3];
    const float* b1     = (const float*)d_in[4];
    const float* W2     = (const float*)d_in[5];
    const float* b2     = (const float*)d_in[6];
    float* out = (float*)d_out;

    int writeLead = (out_size >= NFRAME*NBOX*10) ? 1 : 0;
    const int SMEM3 = (NBOX + 1 + LISTCAP) * 4 + NBOX;
    cudaFuncSetAttribute(k_scan, cudaFuncAttributeMaxDynamicSharedMemorySize, SMEM3);

    k_sort<<<NFRAME, 1024>>>(boxes, scores, labels);
    k_nbr<<<dim3(NBOX/128, NFRAME), 128>>>();
    k_scan<<<NFRAME, 1024, SMEM3>>>();
    k_merge<<<(NFRAME*NBOX)/16, 256>>>(W1, b1, W2, b2, out, writeLead);
}

// round 3
// speedup vs baseline: 3.0559x; 3.0559x over previous
#include <cuda_runtime.h>
#include <math.h>

#define NBOX   4096
#define NFRAME 4
#define CAP    128
#define MAXC   16
#define IOU_T   0.3f
#define SCORE_T 0.2f

// ---------------- scratch (static __device__, no allocations) ----------------
__device__ float d_sbox  [NFRAME*NBOX*7];
__device__ float d_sscore[NFRAME*NBOX];
__device__ float d_slabel[NFRAME*NBOX];
__device__ float d_x1[NFRAME*NBOX], d_x2[NFRAME*NBOX];
__device__ float d_y1[NFRAME*NBOX], d_y2[NFRAME*NBOX];
__device__ float d_areaA[NFRAME*NBOX];
__device__ int   d_V[NFRAME];
__device__ int   d_nbr[NFRAME*NBOX*CAP];
__device__ int   d_deg[NFRAME*NBOX];
__device__ int   d_selfpos[NFRAME*NBOX];
__device__ int   d_clusIdx[NFRAME*NBOX*MAXC];
__device__ int   d_count[NFRAME*NBOX];
__device__ int   d_lead[NFRAME*NBOX];

// ---------------- kernel 1: stable sort by score desc + gather --------------
__global__ void __launch_bounds__(1024) k_sort(const float* __restrict__ boxes,
                                               const float* __restrict__ scores,
                                               const int*   __restrict__ labels)
{
    int f = blockIdx.x, tid = threadIdx.x, lane = tid & 31;
    __shared__ unsigned long long key[NBOX];
    __shared__ int vcount;
    const float* sc = scores + f*NBOX;
    if (tid == 0) vcount = 0;
    for (int i = tid; i < NBOX; i += 1024) {
        float s    = sc[i];
        float skey = (s > SCORE_T) ? s : -INFINITY;
        unsigned u = __float_as_uint(skey);
        u = (u & 0x80000000u) ? ~u : (u | 0x80000000u);   // ascending-sortable
        key[i] = ((unsigned long long)(~u) << 32) | (unsigned)i; // desc score, asc idx (stable)
    }
    __syncthreads();
    for (int k = 2; k <= NBOX; k <<= 1) {
        for (int j = k >> 1; j > 0; j >>= 1) {
            for (int i = tid; i < NBOX; i += 1024) {
                int ixj = i ^ j;
                if (ixj > i) {
                    unsigned long long a = key[i], b = key[ixj];
                    bool up = ((i & k) == 0);
                    if ((a > b) == up) { key[i] = b; key[ixj] = a; }
                }
            }
            __syncthreads();
        }
    }
    for (int r = tid; r < NBOX; r += 1024) {
        int o = (int)(key[r] & 0xFFFFFFFFu);
        const float* bx = boxes + ((size_t)f*NBOX + o)*7;
        float b0 = bx[0], b1 = bx[1], b2 = bx[2], b3 = bx[3],
              b4 = bx[4], b5 = bx[5], b6 = bx[6];
        float s  = sc[o];
        int  lab = labels[f*NBOX + o];
        float off = (float)lab * 10000.0f;          // exact for lab in {0,1,2}
        float cx = b0 + off, cy = b1;
        float hx = b3 * 0.5f, hy = b4 * 0.5f;
        float x1 = cx - hx, x2 = cx + hx, y1 = cy - hy, y2 = cy + hy;
        float area = (x2 - x1) * (y2 - y1);         // replicate reference op order
        int idx = f*NBOX + r;
        float* sb = d_sbox + (size_t)idx*7;
        sb[0]=b0; sb[1]=b1; sb[2]=b2; sb[3]=b3; sb[4]=b4; sb[5]=b5; sb[6]=b6;
        d_sscore[idx] = s; d_slabel[idx] = (float)lab;
        d_x1[idx]=x1; d_x2[idx]=x2; d_y1[idx]=y1; d_y2[idx]=y2; d_areaA[idx]=area;
        unsigned mv = __ballot_sync(0xffffffffu, s > SCORE_T);
        if (lane == 0 && mv) atomicAdd(&vcount, __popc(mv));
    }
    __syncthreads();
    if (tid == 0) d_V[f] = vcount;
}

// ---------------- kernel 2: ascending neighbor lists (IoU > thres) ----------
__global__ void __launch_bounds__(128) k_nbr()
{
    int f   = blockIdx.y;
    int V   = d_V[f];
    int i0  = blockIdx.x * 128;
    int tid = threadIdx.x;
    int i   = i0 + tid;
    int base = f*NBOX;
    bool act = (i < V);
    if (i < NBOX && !act) d_deg[base + i] = 0;
    if (i0 >= V) return;

    float xi1=0,xi2=0,yi1=0,yi2=0,ai=0;
    if (act) { xi1=d_x1[base+i]; xi2=d_x2[base+i];
               yi1=d_y1[base+i]; yi2=d_y2[base+i]; ai=d_areaA[base+i]; }
    __shared__ float sx1[128], sx2[128], sy1[128], sy2[128], sa[128];
    int  cnt  = 0;
    int  sp   = 0;
    int* lst  = d_nbr + ((size_t)(base + i)) * CAP;
    for (int j0 = 0; j0 < V; j0 += 128) {
        __syncthreads();
        int j = j0 + tid;
        if (j < V) { sx1[tid]=d_x1[base+j]; sx2[tid]=d_x2[base+j];
                     sy1[tid]=d_y1[base+j]; sy2[tid]=d_y2[base+j]; sa[tid]=d_areaA[base+j]; }
        __syncthreads();
        int lim = min(128, V - j0);
        if (act) {
            for (int jj = 0; jj < lim; ++jj) {
                float ix = fminf(xi2, sx2[jj]) - fmaxf(xi1, sx1[jj]);
                if (ix > 0.f) {
                    float iy = fminf(yi2, sy2[jj]) - fmaxf(yi1, sy1[jj]);
                    if (iy > 0.f) {
                        float inter = ix * iy;
                        float den   = fmaxf(ai + sa[jj] - inter, 1e-6f);
                        float iou   = inter / den;          // exact fp32 div, matches ref
                        if (iou > IOU_T && cnt < CAP) {
                            if (j0 + jj == i) sp = cnt;      // self position
                            lst[cnt++] = j0 + jj;
                        }
                    }
                }
            }
        }
    }
    if (act) { d_deg[base + i] = cnt; d_selfpos[base + i] = sp; }
}

// ---------------- kernel 3: parallel lex-first greedy via fixpoint ----------
// state: 0=undecided, 1=leader, 2=dead
// i dead   <=> some in-neighbor (j<i, overlap) is a leader
// i leader <=> all in-neighbors dead
// cid(dead i) = min leader among in-neighbors; members of leader j in ascending
// order = [j] + {m in out-nbrs(j) : cid(m)==j}
__global__ void __launch_bounds__(1024) k_scan()
{
    __shared__ unsigned char state[NBOX];
    __shared__ int cidsh[NBOX];
    __shared__ int changed;

    int f = blockIdx.x, tid = threadIdx.x;
    int base = f*NBOX;
    int V = d_V[f];

    for (int i = tid; i < NBOX; i += 1024) {
        state[i] = (i < V) ? (unsigned char)0 : (unsigned char)2;
        d_lead[base + i] = 0;
    }
    __syncthreads();

    for (;;) {
        if (tid == 0) changed = 0;
        __syncthreads();
        for (int i = tid; i < V; i += 1024) {
            if (state[i] != 0) continue;
            const int* lst = d_nbr + ((size_t)(base + i)) * CAP;
            int sp = d_selfpos[base + i];
            bool any1 = false, any0 = false;
            for (int k = 0; k < sp; ++k) {
                unsigned char s = state[lst[k]];
                any1 |= (s == 1); any0 |= (s == 0);
            }
            if (any1)       { state[i] = 2; changed = 1; }
            else if (!any0) { state[i] = 1; changed = 1; }
        }
        __syncthreads();
        if (changed == 0) break;
    }

    // cluster ids
    for (int i = tid; i < V; i += 1024) {
        if (state[i] == 1) { cidsh[i] = i; continue; }
        const int* lst = d_nbr + ((size_t)(base + i)) * CAP;
        int sp = d_selfpos[base + i];
        int c = -1;
        for (int k = 0; k < sp; ++k) {
            int j = lst[k];
            if (state[j] == 1) { c = j; break; }   // ascending => min leader
        }
        cidsh[i] = c;
    }
    __syncthreads();

    // leaders: member lists in ascending order (rank 0 = leader itself)
    for (int i = tid; i < V; i += 1024) {
        if (state[i] != 1) continue;
        int* outl = d_clusIdx + (base + i)*MAXC;
        outl[0] = i;
        const int* lst = d_nbr + ((size_t)(base + i)) * CAP;
        int sp = d_selfpos[base + i], dg = d_deg[base + i];
        int r = 1;
        for (int k = sp + 1; k < dg; ++k) {
            int m = lst[k];
            if (cidsh[m] == i) { if (r < MAXC) outl[r] = m; ++r; }
        }
        d_count[base + i] = (r < MAXC) ? r : MAXC;
        d_lead [base + i] = 1;
    }
}

// ---------------- kernel 4: MLP + softmax merge + output --------------------
__global__ void __launch_bounds__(256) k_merge(const float* __restrict__ W1,
                                               const float* __restrict__ b1,
                                               const float* __restrict__ W2,
                                               const float* __restrict__ b2,
                                               float* __restrict__ out, int writeLead)
{
    __shared__ float sW1[448], sb1[64], sW2[64];
    __shared__ float sb2;
    int tid = threadIdx.x;
    for (int t = tid; t < 448; t += 256) sW1[t] = W1[t];
    if (tid < 64) { sb1[tid] = b1[tid]; sW2[tid] = W2[tid]; }
    if (tid == 0) sb2 = b2[0];
    __syncthreads();

    int g = tid >> 4, l = tid & 15;
    unsigned gm = 0xFFFFu << (tid & 16);     // 16-lane group mask
    int row = blockIdx.x * 16 + g;           // f*NBOX + r
    float* infoOut = out + (size_t)row * 9;
    int lead = d_lead[row];
    if (!lead) {
        if (l == 0) {
            #pragma unroll
            for (int d = 0; d < 9; ++d) infoOut[d] = 0.f;
            if (writeLead) out[(size_t)NFRAME*NBOX*9 + row] = 0.f;
        }
        return;
    }
    int cnt = d_count[row];
    bool ok = l < cnt;
    float c[7];
    int f = row >> 12;
    if (ok) {
        int nb = d_clusIdx[row*MAXC + l];
        const float* sp = d_sbox + ((size_t)(f*NBOX) + nb) * 7;
        #pragma unroll
        for (int d = 0; d < 7; ++d) c[d] = sp[d];
    } else {
        #pragma unroll
        for (int d = 0; d < 7; ++d) c[d] = 0.f;
    }
    float logit;
    if (ok) {
        float lg = 0.f;
        for (int k = 0; k < 64; ++k) {
            float h = sb1[k];
            #pragma unroll
            for (int d = 0; d < 7; ++d) h += c[d] * sW1[d*64 + k];
            h = fmaxf(h, 0.f);
            lg += h * sW2[k];
        }
        logit = lg + sb2;
    } else logit = -1e9f;

    float m = logit;
    #pragma unroll
    for (int o = 8; o; o >>= 1) m = fmaxf(m, __shfl_xor_sync(gm, m, o, 16));
    float p = ok ? expf(logit - m) : 0.f;
    float S = p;
    #pragma unroll
    for (int o = 8; o; o >>= 1) S += __shfl_xor_sync(gm, S, o, 16);
    float w = p / S;
    float mg[7];
    #pragma unroll
    for (int d = 0; d < 7; ++d) {
        float v = w * c[d];
        #pragma unroll
        for (int o = 8; o; o >>= 1) v += __shfl_xor_sync(gm, v, o, 16);
        mg[d] = v;
    }
    if (l == 0) {
        const float* own = d_sbox + (size_t)row * 7;
        infoOut[0] = mg[0]; infoOut[1] = mg[1]; infoOut[2] = mg[2];
        infoOut[3] = (mg[3] <= 0.f) ? own[3] : mg[3];
        infoOut[4] = (mg[4] <= 0.f) ? own[4] : mg[4];
        infoOut[5] = (mg[5] <= 0.f) ? own[5] : mg[5];
        infoOut[6] = mg[6];
        infoOut[7] = d_sscore[row];
        infoOut[8] = d_slabel[row];
        if (writeLead) out[(size_t)NFRAME*NBOX*9 + row] = 1.f;
    }
}

// ---------------- launch -----------------------------------------------------
extern "C" void kernel_launch(void* const* d_in, const int* in_sizes, int n_in,
                              void* d_out, int out_size)
{
    const float* boxes  = (const float*)d_in[0];
    const float* scores = (const float*)d_in[1];
    const int*   labels = (const int*)  d_in[2];
    const float* W1     = (const float*)d_in[3];
    const float* b1     = (const float*)d_in[4];
    const float* W2     = (const float*)d_in[5];
    const float* b2     = (const float*)d_in[6];
    float* out = (float*)d_out;

    int writeLead = (out_size >= NFRAME*NBOX*10) ? 1 : 0;

    k_sort<<<NFRAME, 1024>>>(boxes, scores, labels);
    k_nbr<<<dim3(NBOX/128, NFRAME), 128>>>();
    k_scan<<<NFRAME, 1024>>>();
    k_merge<<<(NFRAME*NBOX)/16, 256>>>(W1, b1, W2, b2, out, writeLead);
}